// round 8
// baseline (speedup 1.0000x reference)
#include <cuda_runtime.h>
#include <math.h>
#include <stdint.h>

#define NN 20000
#define NEMAX 320000
#define GAT_ALPHA 0.2f
#define GAT_EPS 1e-16f

// ---------------- scratch (device globals) ----------------------------------
__device__ float g_Wh [4u * 20000u * 256u];   // per-head GEMM out (h-major)
__device__ float g_x1 [20000u * 1024u];
__device__ float g_x2 [20000u * 1024u];
__device__ float g_ssrc[6 * 20000];
__device__ float g_sdst[6 * 20000];
__device__ int   g_src [NEMAX];
__device__ int   g_dst [NEMAX];
__device__ int   g_cnt [NN];
__device__ int   g_ptr [NN + 1];
__device__ int   g_ofs [NN];
__device__ int   g_csrc[NEMAX];
__device__ int   g_is64;

__device__ __forceinline__ float eluf(float v) { return v > 0.0f ? v : expm1f(v); }
__device__ __forceinline__ uint32_t smem_u32(const void* p) {
    uint32_t a;
    asm("{ .reg .u64 t; cvta.to.shared.u64 t, %1; cvt.u32.u64 %0, t; }" : "=r"(a) : "l"(p));
    return a;
}
__device__ __forceinline__ uint32_t cvt_tf32(float f) {
    uint32_t r; asm("cvt.rna.tf32.f32 %0, %1;" : "=r"(r) : "f"(f)); return r;
}
__device__ __forceinline__ void mma_tf32(float* c, const uint32_t* a, const uint32_t* b) {
    asm("mma.sync.aligned.m16n8k8.row.col.f32.tf32.tf32.f32 "
        "{%0,%1,%2,%3}, {%4,%5,%6,%7}, {%8,%9}, {%0,%1,%2,%3};"
        : "+f"(c[0]), "+f"(c[1]), "+f"(c[2]), "+f"(c[3])
        : "r"(a[0]), "r"(a[1]), "r"(a[2]), "r"(a[3]), "r"(b[0]), "r"(b[1]));
}
__device__ __forceinline__ void cpa16(uint32_t dst, const void* src, int sz) {
    asm volatile("cp.async.ca.shared.global [%0], [%1], 16, %2;"
                 :: "r"(dst), "l"(src), "r"(sz) : "memory");
}
__device__ __forceinline__ void cpa4(uint32_t dst, const void* src, int sz) {
    asm volatile("cp.async.ca.shared.global [%0], [%1], 4, %2;"
                 :: "r"(dst), "l"(src), "r"(sz) : "memory");
}

// ---------------- edge index prep + CSR build -------------------------------
__global__ void detect64_k(const void* p) {
    __shared__ int bad;
    if (threadIdx.x == 0) bad = 0;
    __syncthreads();
    const unsigned int* w = (const unsigned int*)p;
    int i = 1 + 2 * threadIdx.x;
    if (i < 256 && w[i] != 0u) atomicOr(&bad, 1);
    __syncthreads();
    if (threadIdx.x == 0) g_is64 = bad ? 0 : 1;
}
__global__ void zero_cnt_k(int n) {
    int i = blockIdx.x * blockDim.x + threadIdx.x;
    if (i < n) g_cnt[i] = 0;
}
__global__ void convert_hist_k(const void* p, int E) {
    int i = blockIdx.x * blockDim.x + threadIdx.x;
    if (i >= E) return;
    int s, d;
    if (g_is64) {
        const long long* q = (const long long*)p;
        s = (int)q[i]; d = (int)q[E + i];
    } else {
        const int* q = (const int*)p;
        s = q[i]; d = q[E + i];
    }
    g_src[i] = s; g_dst[i] = d;
    atomicAdd(&g_cnt[d], 1);
}
__global__ void scan_k(int n) {
    __shared__ int sums[1024];
    int tid = threadIdx.x;
    int chunk = (n + 1023) / 1024;
    int st = tid * chunk, en = min(st + chunk, n);
    int s = 0;
    for (int i = st; i < en; i++) s += g_cnt[i];
    sums[tid] = s;
    __syncthreads();
    for (int off = 1; off < 1024; off <<= 1) {
        int v = (tid >= off) ? sums[tid - off] : 0;
        __syncthreads();
        sums[tid] += v;
        __syncthreads();
    }
    int run = (tid > 0) ? sums[tid - 1] : 0;
    for (int i = st; i < en; i++) { g_ptr[i] = run; g_ofs[i] = run; run += g_cnt[i]; }
    if (tid == 0) g_ptr[n] = sums[1023];
}
__global__ void scatter_k(int E) {
    int i = blockIdx.x * blockDim.x + threadIdx.x;
    if (i >= E) return;
    int d = g_dst[i];
    int pos = atomicAdd(&g_ofs[d], 1);
    g_csrc[pos] = g_src[i];
}

// ---------------- tf32 mma.sync GEMM, cp.async 3-stage pipeline --------------
// C[((h*M+m)*Fs)+f] = sum_k A[m,k] * W[h,k,f]; B columns f in [Fh,Fs) are zero
// (padding). CTA tile 128x128, 8 warps (2x4), warp tile 64x32, K chunk 32.
#define A_PITCH 36
#define B_PITCH 136
#define A_WORDS (128 * A_PITCH)
#define B_WORDS (32 * B_PITCH)
#define STAGE_WORDS (A_WORDS + B_WORDS)
#define NSTAGE 3
#define GEMM_SMEM_BYTES (NSTAGE * STAGE_WORDS * 4)

__global__ void __launch_bounds__(256)
mma_gemm_k(const float* __restrict__ A, const float* __restrict__ W,
           float* __restrict__ C, int M, int K, int Fh, int Fs, int H,
           int vecA, int vecB) {
    extern __shared__ uint32_t dynsm[];
    int tid = threadIdx.x;
    int wid = tid >> 5, lane = tid & 31;
    int warp_m = wid >> 2, warp_n = wid & 3;
    int row0 = blockIdx.y * 128, col0 = blockIdx.x * 128;
    int Ntot = Fs * H;   // padded column count
    int qrow = lane >> 2, qcol = lane & 3;
    uint32_t smBase = smem_u32(dynsm);

    float acc[4][4][4];
    #pragma unroll
    for (int i = 0; i < 4; i++)
        #pragma unroll
        for (int j = 0; j < 4; j++)
            #pragma unroll
            for (int q = 0; q < 4; q++) acc[i][j][q] = 0.0f;

    int nk = (K + 31) / 32;

    auto issue = [&](int t, int s) {
        int k0 = t * 32;
        uint32_t aA = smBase + (uint32_t)s * STAGE_WORDS * 4;
        uint32_t aB = aA + A_WORDS * 4;
        if (vecA) {
            #pragma unroll
            for (int j = 0; j < 4; j++) {
                int g = tid + 256 * j;
                int r = g >> 3, c4 = (g & 7) * 4;
                int gm = row0 + r, gk = k0 + c4;
                const float* src = A;
                int sz = 0;
                if (gm < M) {
                    int rem = (K - gk) * 4;
                    sz = rem >= 16 ? 16 : (rem > 0 ? rem : 0);
                    if (sz) src = A + (size_t)gm * K + gk;
                }
                cpa16(aA + (uint32_t)(r * A_PITCH + c4) * 4, src, sz);
            }
        } else {
            #pragma unroll
            for (int j = 0; j < 16; j++) {
                int idx = tid + 256 * j;
                int r = idx >> 5, c = idx & 31;
                int gm = row0 + r, gk = k0 + c;
                const float* src = A;
                int sz = 0;
                if (gm < M && gk < K) { src = A + (size_t)gm * K + gk; sz = 4; }
                cpa4(aA + (uint32_t)(r * A_PITCH + c) * 4, src, sz);
            }
        }
        if (vecB) {
            #pragma unroll
            for (int j = 0; j < 4; j++) {
                int g = tid + 256 * j;
                int kk = g >> 5, n4 = (g & 31) * 4;
                int gk = k0 + kk, c = col0 + n4;
                const float* src = W;
                int sz = 0;
                if (gk < K && c < Ntot) {
                    int h = c / Fs, f = c - h * Fs;
                    if (f + 3 < Fh) {
                        src = W + (size_t)h * K * Fh + (size_t)gk * Fh + f;
                        sz = 16;
                    }
                }
                cpa16(aB + (uint32_t)(kk * B_PITCH + n4) * 4, src, sz);
            }
        } else {
            #pragma unroll
            for (int j = 0; j < 16; j++) {
                int idx = tid + 256 * j;
                int kk = idx >> 7, n = idx & 127;
                int gk = k0 + kk, c = col0 + n;
                const float* src = W;
                int sz = 0;
                if (gk < K && c < Ntot) {
                    int h = c / Fs, f = c - h * Fs;
                    if (f < Fh) {
                        src = W + (size_t)h * K * Fh + (size_t)gk * Fh + f;
                        sz = 4;
                    }
                }
                cpa4(aB + (uint32_t)(kk * B_PITCH + n) * 4, src, sz);
            }
        }
        asm volatile("cp.async.commit_group;" ::: "memory");
    };

    issue(0, 0);
    if (nk > 1) issue(1, 1);
    else asm volatile("cp.async.commit_group;" ::: "memory");

    for (int t = 0; t < nk; t++) {
        int s = t % NSTAGE;
        asm volatile("cp.async.wait_group 1;" ::: "memory");
        __syncthreads();
        if (t + 2 < nk) issue(t + 2, (t + 2) % NSTAGE);
        else asm volatile("cp.async.commit_group;" ::: "memory");

        const uint32_t* pAs = dynsm + (size_t)s * STAGE_WORDS;
        const uint32_t* pBs = pAs + A_WORDS;
        #pragma unroll
        for (int kk8 = 0; kk8 < 32; kk8 += 8) {
            uint32_t afr[4][4], bfr[4][2];
            #pragma unroll
            for (int mt = 0; mt < 4; mt++) {
                int rm = warp_m * 64 + mt * 16;
                const uint32_t* p = &pAs[(rm + qrow) * A_PITCH + kk8 + qcol];
                afr[mt][0] = cvt_tf32(__uint_as_float(p[0]));
                afr[mt][1] = cvt_tf32(__uint_as_float(p[8 * A_PITCH]));
                afr[mt][2] = cvt_tf32(__uint_as_float(p[4]));
                afr[mt][3] = cvt_tf32(__uint_as_float(p[8 * A_PITCH + 4]));
            }
            #pragma unroll
            for (int nt = 0; nt < 4; nt++) {
                int nb = warp_n * 32 + nt * 8;
                const uint32_t* p = &pBs[(kk8 + qcol) * B_PITCH + nb + qrow];
                bfr[nt][0] = cvt_tf32(__uint_as_float(p[0]));
                bfr[nt][1] = cvt_tf32(__uint_as_float(p[4 * B_PITCH]));
            }
            #pragma unroll
            for (int mt = 0; mt < 4; mt++)
                #pragma unroll
                for (int nt = 0; nt < 4; nt++)
                    mma_tf32(acc[mt][nt], afr[mt], bfr[nt]);
        }
    }

    // ---- epilogue (writes padding zeros too; keeps padded rows clean) ----
    #pragma unroll
    for (int mt = 0; mt < 4; mt++) {
        #pragma unroll
        for (int half = 0; half < 2; half++) {
            int gm = row0 + warp_m * 64 + mt * 16 + qrow + half * 8;
            if (gm >= M) continue;
            #pragma unroll
            for (int nt = 0; nt < 4; nt++) {
                int gc0 = col0 + warp_n * 32 + nt * 8 + 2 * qcol;
                #pragma unroll
                for (int q = 0; q < 2; q++) {
                    int gc = gc0 + q;
                    if (gc < Ntot) {
                        int h = gc / Fs, f = gc - h * Fs;
                        C[((size_t)h * M + gm) * Fs + f] = acc[mt][nt][half * 2 + q];
                    }
                }
            }
        }
    }
}

// ---------------- per-node attention scores ---------------------------------
__global__ void score_k(const float* __restrict__ Wh, const float* __restrict__ a,
                        float* __restrict__ ssrc, float* __restrict__ sdst,
                        int N, int F, int S) {
    int node = blockIdx.x * (blockDim.x >> 5) + (threadIdx.x >> 5);
    if (node >= N) return;
    int h = blockIdx.y;
    int lane = threadIdx.x & 31;
    const float* row = Wh + ((size_t)h * N + node) * S;
    const float* av  = a + (size_t)h * 2 * F;
    float s1 = 0.0f, s2 = 0.0f;
    for (int f = lane; f < F; f += 32) {
        float w = row[f];
        s1 += w * av[f];
        s2 += w * av[F + f];
    }
    #pragma unroll
    for (int off = 16; off; off >>= 1) {
        s1 += __shfl_xor_sync(0xffffffffu, s1, off);
        s2 += __shfl_xor_sync(0xffffffffu, s2, off);
    }
    if (lane == 0) {
        ssrc[h * N + node] = s1;
        sdst[h * N + node] = s2;
    }
}

// ---------------- fused attention + aggregation (concat layers, F=256) -------
__global__ void __launch_bounds__(256)
agg_concat_k(const float* __restrict__ Wh, const float* __restrict__ ssrc,
             const float* __restrict__ sdst, const float* __restrict__ skip,
             float* __restrict__ out, int N, int H) {
    const int F = 256;
    int wid = (blockIdx.x * blockDim.x + threadIdx.x) >> 5;
    int lane = threadIdx.x & 31;
    if (wid >= N * H) return;
    int d = wid / H, h = wid - d * H;
    int beg = g_ptr[d], end = g_ptr[d + 1];
    float sd = sdst[h * N + d];
    const float* ss = ssrc + (size_t)h * N;

    float m = -INFINITY;
    for (int i = beg + lane; i < end; i += 32) {
        float v = ss[g_csrc[i]] + sd;
        v = v > 0.0f ? v : GAT_ALPHA * v;
        m = fmaxf(m, v);
    }
    #pragma unroll
    for (int off = 16; off; off >>= 1) m = fmaxf(m, __shfl_xor_sync(0xffffffffu, m, off));
    float ssum = 0.0f;
    for (int i = beg + lane; i < end; i += 32) {
        float v = ss[g_csrc[i]] + sd;
        v = v > 0.0f ? v : GAT_ALPHA * v;
        ssum += expf(v - m);
    }
    #pragma unroll
    for (int off = 16; off; off >>= 1) ssum += __shfl_xor_sync(0xffffffffu, ssum, off);
    float inv = 1.0f / (ssum + GAT_EPS);

    float4 acc0 = make_float4(0.f, 0.f, 0.f, 0.f);
    float4 acc1 = make_float4(0.f, 0.f, 0.f, 0.f);
    for (int e = beg; e < end; e++) {
        int s = g_csrc[e];
        float v = ss[s] + sd;
        v = v > 0.0f ? v : GAT_ALPHA * v;
        float att = expf(v - m) * inv;
        const float* w = Wh + ((size_t)h * N + s) * F;
        float4 w0 = *(const float4*)(w + lane * 4);
        float4 w1 = *(const float4*)(w + lane * 4 + 128);
        acc0.x += w0.x * att; acc0.y += w0.y * att;
        acc0.z += w0.z * att; acc0.w += w0.w * att;
        acc1.x += w1.x * att; acc1.y += w1.y * att;
        acc1.z += w1.z * att; acc1.w += w1.w * att;
    }
    size_t base = ((size_t)d * H + h) * F;
    float4 o0, o1;
    o0.x = eluf(acc0.x); o0.y = eluf(acc0.y); o0.z = eluf(acc0.z); o0.w = eluf(acc0.w);
    o1.x = eluf(acc1.x); o1.y = eluf(acc1.y); o1.z = eluf(acc1.z); o1.w = eluf(acc1.w);
    if (skip) {
        float4 k0 = *(const float4*)(skip + base + lane * 4);
        float4 k1 = *(const float4*)(skip + base + lane * 4 + 128);
        o0.x += k0.x; o0.y += k0.y; o0.z += k0.z; o0.w += k0.w;
        o1.x += k1.x; o1.y += k1.y; o1.z += k1.z; o1.w += k1.w;
    }
    o0.x = eluf(o0.x); o0.y = eluf(o0.y); o0.z = eluf(o0.z); o0.w = eluf(o0.w);
    o1.x = eluf(o1.x); o1.y = eluf(o1.y); o1.z = eluf(o1.z); o1.w = eluf(o1.w);
    *(float4*)(out + base + lane * 4)       = o0;
    *(float4*)(out + base + lane * 4 + 128) = o1;
}

// ---------------- fused attention + aggregation (mean layer) ------------------
// Wh stride 128 (padded, zeros beyond F=121). warp per dst.
__global__ void __launch_bounds__(256)
agg_mean_k(const float* __restrict__ Wh, const float* __restrict__ ssrc,
           const float* __restrict__ sdst, float* __restrict__ out,
           int N, int F, int H) {
    const int S = 128;
    int d = (blockIdx.x * blockDim.x + threadIdx.x) >> 5;
    int lane = threadIdx.x & 31;
    if (d >= N) return;
    int beg = g_ptr[d], end = g_ptr[d + 1];
    float4 acc = make_float4(0.f, 0.f, 0.f, 0.f);

    for (int h = 0; h < H; h++) {
        float sd = sdst[h * N + d];
        const float* ss = ssrc + (size_t)h * N;
        float m = -INFINITY;
        for (int i = beg + lane; i < end; i += 32) {
            float v = ss[g_csrc[i]] + sd;
            v = v > 0.0f ? v : GAT_ALPHA * v;
            m = fmaxf(m, v);
        }
        #pragma unroll
        for (int off = 16; off; off >>= 1) m = fmaxf(m, __shfl_xor_sync(0xffffffffu, m, off));
        float ssum = 0.0f;
        for (int i = beg + lane; i < end; i += 32) {
            float v = ss[g_csrc[i]] + sd;
            v = v > 0.0f ? v : GAT_ALPHA * v;
            ssum += expf(v - m);
        }
        #pragma unroll
        for (int off = 16; off; off >>= 1) ssum += __shfl_xor_sync(0xffffffffu, ssum, off);
        float inv = 1.0f / (ssum + GAT_EPS);
        for (int e = beg; e < end; e++) {
            int s = g_csrc[e];
            float v = ss[s] + sd;
            v = v > 0.0f ? v : GAT_ALPHA * v;
            float att = expf(v - m) * inv;
            const float* w = Wh + ((size_t)h * N + s) * S + lane * 4;
            float4 wv = *(const float4*)w;   // padded region holds zeros
            acc.x += wv.x * att; acc.y += wv.y * att;
            acc.z += wv.z * att; acc.w += wv.w * att;
        }
    }
    float invH = 1.0f / (float)H;
    const float* av = (const float*)&acc;
    #pragma unroll
    for (int q = 0; q < 4; q++) {
        int f = lane * 4 + q;
        if (f < F)
            out[(size_t)d * F + f] = 1.0f / (1.0f + expf(-av[q] * invH));
    }
}

// ---------------- host driver -----------------------------------------------
extern "C" void kernel_launch(void* const* d_in, const int* in_sizes, int n_in,
                              void* d_out, int out_size) {
    const float* x    = (const float*)d_in[0];
    const void*  eidx = d_in[1];
    const float* W1   = (const float*)d_in[2];
    const float* a1   = (const float*)d_in[3];
    const float* W2   = (const float*)d_in[4];
    const float* a2   = (const float*)d_in[5];
    const float* W3   = (const float*)d_in[6];
    const float* a3   = (const float*)d_in[7];
    float* out = (float*)d_out;

    int N = NN;
    int E = in_sizes[1] / 2;
    if (E <= 0 || E > NEMAX) E = NEMAX;

    float *Wh, *x1, *x2, *ssrc, *sdst;
    cudaGetSymbolAddress((void**)&Wh,   g_Wh);
    cudaGetSymbolAddress((void**)&x1,   g_x1);
    cudaGetSymbolAddress((void**)&x2,   g_x2);
    cudaGetSymbolAddress((void**)&ssrc, g_ssrc);
    cudaGetSymbolAddress((void**)&sdst, g_sdst);

    cudaFuncSetAttribute(mma_gemm_k, cudaFuncAttributeMaxDynamicSharedMemorySize,
                         GEMM_SMEM_BYTES);

    // --- CSR build (once; shared by all 3 layers) ---
    detect64_k<<<1, 128>>>(eidx);
    zero_cnt_k<<<(N + 255) / 256, 256>>>(N);
    convert_hist_k<<<(E + 255) / 256, 256>>>(eidx, E);
    scan_k<<<1, 1024>>>(N);
    scatter_k<<<(E + 255) / 256, 256>>>(E);

    int mT = (N + 127) / 128;   // 157

    // --- layer 1: Fin=50, Fout=256, H=4, concat ---
    {
        dim3 g(8, mT);
        mma_gemm_k<<<g, 256, GEMM_SMEM_BYTES>>>(x, W1, Wh, N, 50, 256, 256, 4, 0, 1);
        dim3 gs((N + 3) / 4, 4);
        score_k<<<gs, 128>>>(Wh, a1, ssrc, sdst, N, 256, 256);
        agg_concat_k<<<(N * 4 * 32 + 255) / 256, 256>>>(Wh, ssrc, sdst, nullptr, x1, N, 4);
    }
    // --- layer 2: Fin=1024, Fout=256, H=4, concat + skip ---
    {
        dim3 g(8, mT);
        mma_gemm_k<<<g, 256, GEMM_SMEM_BYTES>>>(x1, W2, Wh, N, 1024, 256, 256, 4, 1, 1);
        dim3 gs((N + 3) / 4, 4);
        score_k<<<gs, 128>>>(Wh, a2, ssrc, sdst, N, 256, 256);
        agg_concat_k<<<(N * 4 * 32 + 255) / 256, 256>>>(Wh, ssrc, sdst, x1, x2, N, 4);
    }
    // --- layer 3: Fin=1024, Fout=121 (padded stride 128), H=6, mean + sigmoid ---
    {
        dim3 g(6, mT);   // 6 * 128 = 768 = 6 heads * 128 padded cols
        mma_gemm_k<<<g, 256, GEMM_SMEM_BYTES>>>(x2, W3, Wh, N, 1024, 121, 128, 6, 1, 0);
        dim3 gs((N + 3) / 4, 6);
        score_k<<<gs, 128>>>(Wh, a3, ssrc, sdst, N, 121, 128);
        agg_mean_k<<<(N * 32 + 255) / 256, 256>>>(Wh, ssrc, sdst, out, N, 121, 6);
    }
}

// round 13
// speedup vs baseline: 1.3981x; 1.3981x over previous
#include <cuda_runtime.h>
#include <math.h>
#include <stdint.h>

#define NN 20000
#define NEMAX 320000
#define GAT_ALPHA 0.2f
#define GAT_EPS 1e-16f

// ---------------- scratch (device globals) ----------------------------------
__device__ float g_Wh [4u * 20000u * 256u];   // per-head GEMM out (h-major)
__device__ float g_x1 [20000u * 1024u];
__device__ float g_x2 [20000u * 1024u];
__device__ float g_ssrc[6 * 20000];
__device__ float g_sdst[6 * 20000];
__device__ int   g_src [NEMAX];
__device__ int   g_dst [NEMAX];
__device__ int   g_cnt [NN];
__device__ int   g_ptr [NN + 1];
__device__ int   g_ofs [NN];
__device__ int   g_csrc[NEMAX];
__device__ int   g_is64;

__device__ __forceinline__ float eluf(float v) { return v > 0.0f ? v : expm1f(v); }
__device__ __forceinline__ uint32_t smem_u32(const void* p) {
    uint32_t a;
    asm("{ .reg .u64 t; cvta.to.shared.u64 t, %1; cvt.u32.u64 %0, t; }" : "=r"(a) : "l"(p));
    return a;
}
__device__ __forceinline__ uint32_t cvt_tf32(float f) {
    uint32_t r; asm("cvt.rna.tf32.f32 %0, %1;" : "=r"(r) : "f"(f)); return r;
}
__device__ __forceinline__ void mma_tf32(float* c, const uint32_t* a, const uint32_t* b) {
    asm("mma.sync.aligned.m16n8k8.row.col.f32.tf32.tf32.f32 "
        "{%0,%1,%2,%3}, {%4,%5,%6,%7}, {%8,%9}, {%0,%1,%2,%3};"
        : "+f"(c[0]), "+f"(c[1]), "+f"(c[2]), "+f"(c[3])
        : "r"(a[0]), "r"(a[1]), "r"(a[2]), "r"(a[3]), "r"(b[0]), "r"(b[1]));
}
__device__ __forceinline__ void cpa16(uint32_t dst, const void* src, int sz) {
    asm volatile("cp.async.ca.shared.global [%0], [%1], 16, %2;"
                 :: "r"(dst), "l"(src), "r"(sz) : "memory");
}
__device__ __forceinline__ void cpa4(uint32_t dst, const void* src, int sz) {
    asm volatile("cp.async.ca.shared.global [%0], [%1], 4, %2;"
                 :: "r"(dst), "l"(src), "r"(sz) : "memory");
}

// ---------------- edge index prep + CSR build -------------------------------
__global__ void detect64_k(const void* p) {
    __shared__ int bad;
    if (threadIdx.x == 0) bad = 0;
    __syncthreads();
    const unsigned int* w = (const unsigned int*)p;
    int i = 1 + 2 * threadIdx.x;
    if (i < 256 && w[i] != 0u) atomicOr(&bad, 1);
    __syncthreads();
    if (threadIdx.x == 0) g_is64 = bad ? 0 : 1;
}
__global__ void zero_cnt_k(int n) {
    int i = blockIdx.x * blockDim.x + threadIdx.x;
    if (i < n) g_cnt[i] = 0;
}
__global__ void convert_hist_k(const void* p, int E) {
    int i = blockIdx.x * blockDim.x + threadIdx.x;
    if (i >= E) return;
    int s, d;
    if (g_is64) {
        const long long* q = (const long long*)p;
        s = (int)q[i]; d = (int)q[E + i];
    } else {
        const int* q = (const int*)p;
        s = q[i]; d = q[E + i];
    }
    g_src[i] = s; g_dst[i] = d;
    atomicAdd(&g_cnt[d], 1);
}
__global__ void scan_k(int n) {
    __shared__ int sums[1024];
    int tid = threadIdx.x;
    int chunk = (n + 1023) / 1024;
    int st = tid * chunk, en = min(st + chunk, n);
    int s = 0;
    for (int i = st; i < en; i++) s += g_cnt[i];
    sums[tid] = s;
    __syncthreads();
    for (int off = 1; off < 1024; off <<= 1) {
        int v = (tid >= off) ? sums[tid - off] : 0;
        __syncthreads();
        sums[tid] += v;
        __syncthreads();
    }
    int run = (tid > 0) ? sums[tid - 1] : 0;
    for (int i = st; i < en; i++) { g_ptr[i] = run; g_ofs[i] = run; run += g_cnt[i]; }
    if (tid == 0) g_ptr[n] = sums[1023];
}
__global__ void scatter_k(int E) {
    int i = blockIdx.x * blockDim.x + threadIdx.x;
    if (i >= E) return;
    int d = g_dst[i];
    int pos = atomicAdd(&g_ofs[d], 1);
    g_csrc[pos] = g_src[i];
}

// ---------------- tf32 mma.sync GEMM, cp.async 3-stage pipeline --------------
// C[((h*M+m)*Fh)+f] = sum_k A[m,k] * W[h,k,f]
// CTA tile 128x128, 8 warps (2x4), warp tile 64x32, K chunk 32.
#define A_PITCH 36
#define B_PITCH 136
#define A_WORDS (128 * A_PITCH)
#define B_WORDS (32 * B_PITCH)
#define STAGE_WORDS (A_WORDS + B_WORDS)
#define NSTAGE 3
#define GEMM_SMEM_BYTES (NSTAGE * STAGE_WORDS * 4)

__global__ void __launch_bounds__(256)
mma_gemm_k(const float* __restrict__ A, const float* __restrict__ W,
           float* __restrict__ C, int M, int K, int Fh, int H,
           int vecA, int vecB) {
    extern __shared__ uint32_t dynsm[];
    int tid = threadIdx.x;
    int wid = tid >> 5, lane = tid & 31;
    int warp_m = wid >> 2, warp_n = wid & 3;
    int row0 = blockIdx.y * 128, col0 = blockIdx.x * 128;
    int Ntot = Fh * H;
    int qrow = lane >> 2, qcol = lane & 3;
    uint32_t smBase = smem_u32(dynsm);

    float acc[4][4][4];
    #pragma unroll
    for (int i = 0; i < 4; i++)
        #pragma unroll
        for (int j = 0; j < 4; j++)
            #pragma unroll
            for (int q = 0; q < 4; q++) acc[i][j][q] = 0.0f;

    int nk = (K + 31) / 32;

    auto issue = [&](int t, int s) {
        int k0 = t * 32;
        uint32_t aA = smBase + (uint32_t)s * STAGE_WORDS * 4;
        uint32_t aB = aA + A_WORDS * 4;
        if (vecA) {
            #pragma unroll
            for (int j = 0; j < 4; j++) {
                int g = tid + 256 * j;
                int r = g >> 3, c4 = (g & 7) * 4;
                int gm = row0 + r, gk = k0 + c4;
                const float* src = A;
                int sz = 0;
                if (gm < M) {
                    int rem = (K - gk) * 4;
                    sz = rem >= 16 ? 16 : (rem > 0 ? rem : 0);
                    if (sz) src = A + (size_t)gm * K + gk;
                }
                cpa16(aA + (uint32_t)(r * A_PITCH + c4) * 4, src, sz);
            }
        } else {
            #pragma unroll
            for (int j = 0; j < 16; j++) {
                int idx = tid + 256 * j;
                int r = idx >> 5, c = idx & 31;
                int gm = row0 + r, gk = k0 + c;
                const float* src = A;
                int sz = 0;
                if (gm < M && gk < K) { src = A + (size_t)gm * K + gk; sz = 4; }
                cpa4(aA + (uint32_t)(r * A_PITCH + c) * 4, src, sz);
            }
        }
        if (vecB) {
            #pragma unroll
            for (int j = 0; j < 4; j++) {
                int g = tid + 256 * j;
                int kk = g >> 5, n4 = (g & 31) * 4;
                int gk = k0 + kk, c = col0 + n4;
                const float* src = W;
                int sz = 0;
                if (gk < K && c < Ntot) {
                    int h = c / Fh, f = c - h * Fh;
                    src = W + (size_t)h * K * Fh + (size_t)gk * Fh + f;
                    sz = 16;
                }
                cpa16(aB + (uint32_t)(kk * B_PITCH + n4) * 4, src, sz);
            }
        } else {
            #pragma unroll
            for (int j = 0; j < 16; j++) {
                int idx = tid + 256 * j;
                int kk = idx >> 7, n = idx & 127;
                int gk = k0 + kk, c = col0 + n;
                const float* src = W;
                int sz = 0;
                if (gk < K && c < Ntot) {
                    int h = c / Fh, f = c - h * Fh;
                    src = W + (size_t)h * K * Fh + (size_t)gk * Fh + f;
                    sz = 4;
                }
                cpa4(aB + (uint32_t)(kk * B_PITCH + n) * 4, src, sz);
            }
        }
        asm volatile("cp.async.commit_group;" ::: "memory");
    };

    issue(0, 0);
    if (nk > 1) issue(1, 1);
    else asm volatile("cp.async.commit_group;" ::: "memory");

    for (int t = 0; t < nk; t++) {
        int s = t % NSTAGE;
        asm volatile("cp.async.wait_group 1;" ::: "memory");
        __syncthreads();
        if (t + 2 < nk) issue(t + 2, (t + 2) % NSTAGE);
        else asm volatile("cp.async.commit_group;" ::: "memory");

        const uint32_t* pAs = dynsm + (size_t)s * STAGE_WORDS;
        const uint32_t* pBs = pAs + A_WORDS;
        #pragma unroll
        for (int kk8 = 0; kk8 < 32; kk8 += 8) {
            uint32_t afr[4][4], bfr[4][2];
            #pragma unroll
            for (int mt = 0; mt < 4; mt++) {
                int rm = warp_m * 64 + mt * 16;
                const uint32_t* p = &pAs[(rm + qrow) * A_PITCH + kk8 + qcol];
                afr[mt][0] = cvt_tf32(__uint_as_float(p[0]));
                afr[mt][1] = cvt_tf32(__uint_as_float(p[8 * A_PITCH]));
                afr[mt][2] = cvt_tf32(__uint_as_float(p[4]));
                afr[mt][3] = cvt_tf32(__uint_as_float(p[8 * A_PITCH + 4]));
            }
            #pragma unroll
            for (int nt = 0; nt < 4; nt++) {
                int nb = warp_n * 32 + nt * 8;
                const uint32_t* p = &pBs[(kk8 + qcol) * B_PITCH + nb + qrow];
                bfr[nt][0] = cvt_tf32(__uint_as_float(p[0]));
                bfr[nt][1] = cvt_tf32(__uint_as_float(p[4 * B_PITCH]));
            }
            #pragma unroll
            for (int mt = 0; mt < 4; mt++)
                #pragma unroll
                for (int nt = 0; nt < 4; nt++)
                    mma_tf32(acc[mt][nt], afr[mt], bfr[nt]);
        }
    }

    // ---- epilogue ----
    #pragma unroll
    for (int mt = 0; mt < 4; mt++) {
        #pragma unroll
        for (int half = 0; half < 2; half++) {
            int gm = row0 + warp_m * 64 + mt * 16 + qrow + half * 8;
            if (gm >= M) continue;
            #pragma unroll
            for (int nt = 0; nt < 4; nt++) {
                int gc0 = col0 + warp_n * 32 + nt * 8 + 2 * qcol;
                #pragma unroll
                for (int q = 0; q < 2; q++) {
                    int gc = gc0 + q;
                    if (gc < Ntot) {
                        int h = gc / Fh, f = gc - h * Fh;
                        C[((size_t)h * M + gm) * Fh + f] = acc[mt][nt][half * 2 + q];
                    }
                }
            }
        }
    }
}

// ---------------- per-node attention scores ---------------------------------
__global__ void score_k(const float* __restrict__ Wh, const float* __restrict__ a,
                        float* __restrict__ ssrc, float* __restrict__ sdst,
                        int N, int F) {
    int node = blockIdx.x * (blockDim.x >> 5) + (threadIdx.x >> 5);
    if (node >= N) return;
    int h = blockIdx.y;
    int lane = threadIdx.x & 31;
    const float* row = Wh + ((size_t)h * N + node) * F;
    const float* av  = a + (size_t)h * 2 * F;
    float s1 = 0.0f, s2 = 0.0f;
    for (int f = lane; f < F; f += 32) {
        float w = row[f];
        s1 += w * av[f];
        s2 += w * av[F + f];
    }
    #pragma unroll
    for (int off = 16; off; off >>= 1) {
        s1 += __shfl_xor_sync(0xffffffffu, s1, off);
        s2 += __shfl_xor_sync(0xffffffffu, s2, off);
    }
    if (lane == 0) {
        ssrc[h * N + node] = s1;
        sdst[h * N + node] = s2;
    }
}

// ---------------- fused attention + aggregation (concat layers) -------------
// HEAD-MAJOR warp mapping: concurrent warps share one ~20MB head slab of Wh,
// keeping the row-gather working set L2-resident.
template <int NJ>
__global__ void __launch_bounds__(256)
agg_concat_k(const float* __restrict__ Wh, const float* __restrict__ ssrc,
             const float* __restrict__ sdst, const float* __restrict__ skip,
             float* __restrict__ out, int N, int F, int H) {
    int wid = (blockIdx.x * blockDim.x + threadIdx.x) >> 5;
    int lane = threadIdx.x & 31;
    if (wid >= N * H) return;
    int h = wid / N, d = wid - h * N;     // head-major
    int beg = g_ptr[d], end = g_ptr[d + 1];
    float sd = sdst[h * N + d];
    const float* ss = ssrc + (size_t)h * N;

    float m = -INFINITY;
    for (int i = beg + lane; i < end; i += 32) {
        float v = ss[g_csrc[i]] + sd;
        v = v > 0.0f ? v : GAT_ALPHA * v;
        m = fmaxf(m, v);
    }
    #pragma unroll
    for (int off = 16; off; off >>= 1) m = fmaxf(m, __shfl_xor_sync(0xffffffffu, m, off));
    float ssum = 0.0f;
    for (int i = beg + lane; i < end; i += 32) {
        float v = ss[g_csrc[i]] + sd;
        v = v > 0.0f ? v : GAT_ALPHA * v;
        ssum += expf(v - m);
    }
    #pragma unroll
    for (int off = 16; off; off >>= 1) ssum += __shfl_xor_sync(0xffffffffu, ssum, off);
    float inv = 1.0f / (ssum + GAT_EPS);

    float acc[NJ];
    #pragma unroll
    for (int j = 0; j < NJ; j++) acc[j] = 0.0f;
    for (int e = beg; e < end; e++) {
        int s = g_csrc[e];
        float v = ss[s] + sd;
        v = v > 0.0f ? v : GAT_ALPHA * v;
        float att = expf(v - m) * inv;
        const float* w = Wh + ((size_t)h * N + s) * F;
        #pragma unroll
        for (int j = 0; j < NJ; j++) acc[j] += w[lane + 32 * j] * att;
    }
    size_t base = ((size_t)d * H + h) * F;
    #pragma unroll
    for (int j = 0; j < NJ; j++) {
        float v = eluf(acc[j]);
        if (skip) v += skip[base + lane + 32 * j];
        out[base + lane + 32 * j] = eluf(v);
    }
}

// ---------------- fused attention + aggregation (mean layer) ----------------
template <int NJ>
__global__ void __launch_bounds__(256)
agg_mean_k(const float* __restrict__ Wh, const float* __restrict__ ssrc,
           const float* __restrict__ sdst, float* __restrict__ out,
           int N, int F, int H) {
    int d = (blockIdx.x * blockDim.x + threadIdx.x) >> 5;
    int lane = threadIdx.x & 31;
    if (d >= N) return;
    int beg = g_ptr[d], end = g_ptr[d + 1];
    float accs[NJ];
    #pragma unroll
    for (int j = 0; j < NJ; j++) accs[j] = 0.0f;

    for (int h = 0; h < H; h++) {
        float sd = sdst[h * N + d];
        const float* ss = ssrc + (size_t)h * N;
        float m = -INFINITY;
        for (int i = beg + lane; i < end; i += 32) {
            float v = ss[g_csrc[i]] + sd;
            v = v > 0.0f ? v : GAT_ALPHA * v;
            m = fmaxf(m, v);
        }
        #pragma unroll
        for (int off = 16; off; off >>= 1) m = fmaxf(m, __shfl_xor_sync(0xffffffffu, m, off));
        float ssum = 0.0f;
        for (int i = beg + lane; i < end; i += 32) {
            float v = ss[g_csrc[i]] + sd;
            v = v > 0.0f ? v : GAT_ALPHA * v;
            ssum += expf(v - m);
        }
        #pragma unroll
        for (int off = 16; off; off >>= 1) ssum += __shfl_xor_sync(0xffffffffu, ssum, off);
        float inv = 1.0f / (ssum + GAT_EPS);
        for (int e = beg; e < end; e++) {
            int s = g_csrc[e];
            float v = ss[s] + sd;
            v = v > 0.0f ? v : GAT_ALPHA * v;
            float att = expf(v - m) * inv;
            const float* w = Wh + ((size_t)h * N + s) * F;
            #pragma unroll
            for (int j = 0; j < NJ; j++) {
                int f = lane + 32 * j;
                if (f < F) accs[j] += w[f] * att;
            }
        }
    }
    float invH = 1.0f / (float)H;
    #pragma unroll
    for (int j = 0; j < NJ; j++) {
        int f = lane + 32 * j;
        if (f < F) out[(size_t)d * F + f] = 1.0f / (1.0f + expf(-accs[j] * invH));
    }
}

// ---------------- host driver -----------------------------------------------
extern "C" void kernel_launch(void* const* d_in, const int* in_sizes, int n_in,
                              void* d_out, int out_size) {
    const float* x    = (const float*)d_in[0];
    const void*  eidx = d_in[1];
    const float* W1   = (const float*)d_in[2];
    const float* a1   = (const float*)d_in[3];
    const float* W2   = (const float*)d_in[4];
    const float* a2   = (const float*)d_in[5];
    const float* W3   = (const float*)d_in[6];
    const float* a3   = (const float*)d_in[7];
    float* out = (float*)d_out;

    int N = NN;
    int E = in_sizes[1] / 2;
    if (E <= 0 || E > NEMAX) E = NEMAX;

    float *Wh, *x1, *x2, *ssrc, *sdst;
    cudaGetSymbolAddress((void**)&Wh,   g_Wh);
    cudaGetSymbolAddress((void**)&x1,   g_x1);
    cudaGetSymbolAddress((void**)&x2,   g_x2);
    cudaGetSymbolAddress((void**)&ssrc, g_ssrc);
    cudaGetSymbolAddress((void**)&sdst, g_sdst);

    cudaFuncSetAttribute(mma_gemm_k, cudaFuncAttributeMaxDynamicSharedMemorySize,
                         GEMM_SMEM_BYTES);

    // --- CSR build (once; shared by all 3 layers) ---
    detect64_k<<<1, 128>>>(eidx);
    zero_cnt_k<<<(N + 255) / 256, 256>>>(N);
    convert_hist_k<<<(E + 255) / 256, 256>>>(eidx, E);
    scan_k<<<1, 1024>>>(N);
    scatter_k<<<(E + 255) / 256, 256>>>(E);

    int mT = (N + 127) / 128;   // 157

    // --- layer 1: Fin=50, Fout=256, H=4, concat ---
    {
        dim3 g(8, mT);
        mma_gemm_k<<<g, 256, GEMM_SMEM_BYTES>>>(x, W1, Wh, N, 50, 256, 4, 0, 1);
        dim3 gs((N + 3) / 4, 4);
        score_k<<<gs, 128>>>(Wh, a1, ssrc, sdst, N, 256);
        agg_concat_k<8><<<(N * 4 * 32 + 255) / 256, 256>>>(Wh, ssrc, sdst, nullptr, x1, N, 256, 4);
    }
    // --- layer 2: Fin=1024, Fout=256, H=4, concat + skip ---
    {
        dim3 g(8, mT);
        mma_gemm_k<<<g, 256, GEMM_SMEM_BYTES>>>(x1, W2, Wh, N, 1024, 256, 4, 1, 1);
        dim3 gs((N + 3) / 4, 4);
        score_k<<<gs, 128>>>(Wh, a2, ssrc, sdst, N, 256);
        agg_concat_k<8><<<(N * 4 * 32 + 255) / 256, 256>>>(Wh, ssrc, sdst, x1, x2, N, 256, 4);
    }
    // --- layer 3: Fin=1024, Fout=121, H=6, mean + sigmoid ---
    {
        dim3 g(6, mT);
        mma_gemm_k<<<g, 256, GEMM_SMEM_BYTES>>>(x2, W3, Wh, N, 1024, 121, 6, 1, 0);
        dim3 gs((N + 3) / 4, 6);
        score_k<<<gs, 128>>>(Wh, a3, ssrc, sdst, N, 121);
        agg_mean_k<4><<<(N * 32 + 255) / 256, 256>>>(Wh, ssrc, sdst, out, N, 121, 6);
    }
}